// round 17
// baseline (speedup 1.0000x reference)
#include <cuda_runtime.h>
#include <cuda_bf16.h>

// CRF loss — tensor-core scan. Each CTA batches 16 rows: step = mma.sync
// A[16x128] x E[128x128] (bf16, f32 accum), state ping-pongs in smem.
// grid = 32: bids 0..15 FORWARD groups (t=1..511 -> A_511), bids 16..31
// BACKWARD groups (init t=1023, scaled t=1022..512, final plain matvec ->
// B_511). Join per 16-row group: Z_r = sum_j A_511[r][j]*B_511[r][j].
// E in B-fragments (64 regs, loaded once). Emissions LDG'd at each thread's
// accumulator positions (prefetched 1 step ahead), exp'd off-chain.
// Per-row exact power-of-2 renorm every 4 steps from exponent of S[r][0].

namespace {
constexpr int TT = 128;
constexpr int SS = 1024;
constexpr int NB = 256;
constexpr int NROWS = 16;
constexpr int NGRP = NB / NROWS;   // 16
constexpr int GRID = 2 * NGRP;     // 32
constexpr int SP = 136;            // smem row pitch in bf16 (16B-aligned rows, conflict-free)
constexpr int START_TAG = 126;
constexpr int END_TAG = 127;
}

typedef unsigned int u32;
typedef unsigned short u16;

__device__ float g_avec[NB][TT];
__device__ float g_bvec[NB][TT];
__device__ int g_lea[NB];
__device__ int g_leb[NB];
__device__ double g_goldg[NGRP];
__device__ double g_part[NB];
__device__ u32 g_cnt[NGRP];
__device__ u32 g_ticket;

__device__ __forceinline__ u32 smem_u32(const void* p) {
    return (u32)__cvta_generic_to_shared(p);
}

#define MMA_BF16(c, a, b0, b1)                                              \
    asm volatile(                                                           \
        "mma.sync.aligned.m16n8k16.row.col.f32.bf16.bf16.f32 "              \
        "{%0,%1,%2,%3}, {%4,%5,%6,%7}, {%8,%9}, {%0,%1,%2,%3};"             \
        : "+f"((c)[0]), "+f"((c)[1]), "+f"((c)[2]), "+f"((c)[3])            \
        : "r"((a)[0]), "r"((a)[1]), "r"((a)[2]), "r"((a)[3]),               \
          "r"(b0), "r"(b1))

#define LDSM4(A, addr)                                                      \
    asm volatile(                                                           \
        "ldmatrix.sync.aligned.m8n8.x4.shared.b16 {%0,%1,%2,%3}, [%4];"     \
        : "=r"((A)[0]), "=r"((A)[1]), "=r"((A)[2]), "=r"((A)[3])            \
        : "r"(addr))

__device__ __forceinline__ u32 packbf2(float lo, float hi) {
    __nv_bfloat162 p = __floats2bfloat162_rn(lo, hi);
    return *reinterpret_cast<u32*>(&p);
}

// per-row renorm scale from exponent of S[r][0] (bf16 exponent == f32's)
__device__ __forceinline__ float rowscale(const __nv_bfloat16* srd, int r, int& le) {
    u16 b = reinterpret_cast<const u16*>(srd)[r * SP];
    int ex = (int)((b >> 7) & 0xffu) - 127;
    ex = max(-100, min(100, ex));
    le += ex;
    return __int_as_float((127 - ex) << 23);
}

// One mma scan step. ef holds THIS step's raw emissions (8 float2);
// prefetches the next step's from p1/p2 (advanced by caller).
template <bool SC>
__device__ __forceinline__ void mma_step(
    u32 a_addr, __nv_bfloat16* swr,
    const u32 (&B0a)[32], const u32 (&B1a)[32],
    float2 (&ef)[8], const float* np1, const float* np2,
    float sc1, float sc2, int r1, int r2, int colq) {
    // exp current emissions (off critical chain)
    float e0[8], e1[8];
#pragma unroll
    for (int q = 0; q < 4; q++) {
        float a = __expf(ef[q].x), b = __expf(ef[q].y);
        float c = __expf(ef[4 + q].x), d = __expf(ef[4 + q].y);
        if (SC) { a *= sc1; b *= sc1; c *= sc2; d *= sc2; }
        e0[2 * q] = a; e0[2 * q + 1] = b;
        e1[2 * q] = c; e1[2 * q + 1] = d;
    }
    // prefetch next step's emissions
#pragma unroll
    for (int q = 0; q < 4; q++) {
        ef[q]     = *reinterpret_cast<const float2*>(np1 + 8 * q);
        ef[4 + q] = *reinterpret_cast<const float2*>(np2 + 8 * q);
    }
    // A fragments for all 8 k-tiles
    u32 A[8][4];
#pragma unroll
    for (int kt = 0; kt < 8; kt++) LDSM4(A[kt], a_addr + kt * 32);
    // split-k accumulation: chains of 4
    float cL[4][4], cH[4][4];
#pragma unroll
    for (int q = 0; q < 4; q++)
#pragma unroll
        for (int i = 0; i < 4; i++) { cL[q][i] = 0.f; cH[q][i] = 0.f; }
#pragma unroll
    for (int kt = 0; kt < 4; kt++)
#pragma unroll
        for (int q = 0; q < 4; q++) {
            MMA_BF16(cL[q], A[kt],     B0a[q * 8 + kt],     B1a[q * 8 + kt]);
            MMA_BF16(cH[q], A[kt + 4], B0a[q * 8 + kt + 4], B1a[q * 8 + kt + 4]);
        }
    // epilogue: emission multiply, cvt, store to write buffer
#pragma unroll
    for (int q = 0; q < 4; q++) {
        float c0 = (cL[q][0] + cH[q][0]) * e0[2 * q];
        float c1 = (cL[q][1] + cH[q][1]) * e0[2 * q + 1];
        float c2 = (cL[q][2] + cH[q][2]) * e1[2 * q];
        float c3 = (cL[q][3] + cH[q][3]) * e1[2 * q + 1];
        *reinterpret_cast<u32*>(swr + r1 * SP + colq + 8 * q) = packbf2(c0, c1);
        *reinterpret_cast<u32*>(swr + r2 * SP + colq + 8 * q) = packbf2(c2, c3);
    }
    __syncthreads();
}

// 511 steps. DT = +TT (fwd) / -TT (bwd). p1_/p2_ point at step-0 emissions.
// Final state ends in S1.
template <int DT>
__device__ __forceinline__ void scan511(
    __nv_bfloat16* S0p, __nv_bfloat16* S1p, u32 a0, u32 a1,
    const u32 (&B0a)[32], const u32 (&B1a)[32],
    const float* p1, const float* p2,
    int r1, int r2, int colq, int& le1, int& le2) {
    float2 ef[8];
#pragma unroll
    for (int q = 0; q < 4; q++) {
        ef[q]     = *reinterpret_cast<const float2*>(p1 + 8 * q);
        ef[4 + q] = *reinterpret_cast<const float2*>(p2 + 8 * q);
    }
    p1 += DT; p2 += DT;
    // group 0: 4 unscaled steps (state one-hot / fresh init)
    mma_step<false>(a0, S1p, B0a, B1a, ef, p1, p2, 1.f, 1.f, r1, r2, colq); p1 += DT; p2 += DT;
    mma_step<false>(a1, S0p, B0a, B1a, ef, p1, p2, 1.f, 1.f, r1, r2, colq); p1 += DT; p2 += DT;
    mma_step<false>(a0, S1p, B0a, B1a, ef, p1, p2, 1.f, 1.f, r1, r2, colq); p1 += DT; p2 += DT;
    mma_step<false>(a1, S0p, B0a, B1a, ef, p1, p2, 1.f, 1.f, r1, r2, colq); p1 += DT; p2 += DT;
    // groups 1..126 (504 steps), scale at group top
#pragma unroll 1
    for (int g = 1; g < 127; g++) {
        float sc1 = rowscale(S0p, r1, le1);
        float sc2 = rowscale(S0p, r2, le2);
        mma_step<true >(a0, S1p, B0a, B1a, ef, p1, p2, sc1, sc2, r1, r2, colq); p1 += DT; p2 += DT;
        mma_step<false>(a1, S0p, B0a, B1a, ef, p1, p2, 1.f, 1.f, r1, r2, colq); p1 += DT; p2 += DT;
        mma_step<false>(a0, S1p, B0a, B1a, ef, p1, p2, 1.f, 1.f, r1, r2, colq); p1 += DT; p2 += DT;
        mma_step<false>(a1, S0p, B0a, B1a, ef, p1, p2, 1.f, 1.f, r1, r2, colq); p1 += DT; p2 += DT;
    }
    // remainder: steps 508..510 (scale at first) -> final state in S1
    {
        float sc1 = rowscale(S0p, r1, le1);
        float sc2 = rowscale(S0p, r2, le2);
        mma_step<true >(a0, S1p, B0a, B1a, ef, p1, p2, sc1, sc2, r1, r2, colq); p1 += DT; p2 += DT;
        mma_step<false>(a1, S0p, B0a, B1a, ef, p1, p2, 1.f, 1.f, r1, r2, colq); p1 += DT; p2 += DT;
        mma_step<false>(a0, S1p, B0a, B1a, ef, p1, p2, 1.f, 1.f, r1, r2, colq);
    }
}

__global__ void __launch_bounds__(128, 1)
crf_kernel(const float* __restrict__ em, const int* __restrict__ tags,
           const float* __restrict__ trans, float* __restrict__ out) {
    const int bid = blockIdx.x;
    const int j = threadIdx.x;
    const int l = j & 31;
    const int w = j >> 5;
    const int tig = l & 3;
    const int gid = l >> 2;
    const int r1 = gid, r2 = gid + 8;
    const int colq = 32 * w + 2 * tig;  // epilogue/emission col base (q adds 8q)

    __shared__ __align__(16) __nv_bfloat16 S[2][NROWS * SP];
    __shared__ __align__(16) float red[8];
    __shared__ double sd[4];
    __shared__ int sjoin, sfinal;

    const bool isFwd = (bid < NGRP);
    const int grp = isFwd ? bid : bid - NGRP;
    const int base = grp * NROWS;

    // ---- B fragments of E (fwd) / E^T (bwd), loaded once: 64 regs ----
    u32 B0a[32], B1a[32];
    if (isFwd) {
#pragma unroll
        for (int q = 0; q < 4; q++)
#pragma unroll
            for (int kt = 0; kt < 8; kt++) {
                int C = 32 * w + 8 * q + gid;
                int K0 = 16 * kt + 2 * tig;
                B0a[q * 8 + kt] = packbf2(__expf(trans[K0 * TT + C]),
                                          __expf(trans[(K0 + 1) * TT + C]));
                B1a[q * 8 + kt] = packbf2(__expf(trans[(K0 + 8) * TT + C]),
                                          __expf(trans[(K0 + 9) * TT + C]));
            }
    } else {
#pragma unroll
        for (int q = 0; q < 4; q++)
#pragma unroll
            for (int kt = 0; kt < 8; kt++) {
                int C = 32 * w + 8 * q + gid;
                int K0 = 16 * kt + 2 * tig;
                B0a[q * 8 + kt] = packbf2(__expf(trans[C * TT + K0]),
                                          __expf(trans[C * TT + K0 + 1]));
                B1a[q * 8 + kt] = packbf2(__expf(trans[C * TT + K0 + 8]),
                                          __expf(trans[C * TT + K0 + 9]));
            }
    }

    // ---- mTE: max over j of trans[END][j] ----
    float tEj = trans[END_TAG * TT + j];
    {
        float m = tEj;
#pragma unroll
        for (int o = 16; o > 0; o >>= 1)
            m = fmaxf(m, __shfl_xor_sync(0xffffffffu, m, o));
        if (l == 0) red[w] = m;
    }
    __syncthreads();
    const float mTE = fmaxf(fmaxf(red[0], red[1]), fmaxf(red[2], red[3]));
    __syncthreads();

    // ---- init state S[0] ----
    if (isFwd) {
#pragma unroll
        for (int idx = 0; idx < NROWS; idx++)
            S[0][idx * SP + j] = __float2bfloat16_rn(j == START_TAG ? 1.f : 0.f);
    } else {
#pragma unroll
        for (int idx = 0; idx < NROWS; idx++) {
            float v = em[(size_t)(base + idx) * SS * TT + (size_t)1023 * TT + j];
            S[0][idx * SP + j] =
                __float2bfloat16_rn(__expf(v + trans[END_TAG * TT + j] - mTE));
        }
    }
    __syncthreads();

    // ---- ldmatrix lane addresses for both buffers ----
    const u32 R = (l & 7) + 8 * ((l >> 3) & 1);
    const u32 colb = (l >> 4) * 8;
    const u32 a0 = smem_u32(&S[0][0]) + (R * SP + colb) * 2;
    const u32 a1 = smem_u32(&S[1][0]) + (R * SP + colb) * 2;

    int le1 = 0, le2 = 0;

    if (isFwd) {
        // emission pointers at t0 = 1 for this thread's rows/cols
        const float* p1 = em + (size_t)(base + r1) * SS * TT + (size_t)1 * TT + colq;
        const float* p2 = em + (size_t)(base + r2) * SS * TT + (size_t)1 * TT + colq;
        scan511<+TT>(&S[0][0], &S[1][0], a0, a1, B0a, B1a, p1, p2,
                     r1, r2, colq, le1, le2);
        // A_511 (bf16) in S[1] -> g_avec
#pragma unroll
        for (int rr = 0; rr < NROWS; rr++)
            g_avec[base + rr][j] = __bfloat162float(S[1][rr * SP + j]);
        if (w == 0 && tig == 0) {
            g_lea[base + gid] = le1;
            g_lea[base + gid + 8] = le2;
        }
        // ---- gold (aggregated over the 16 rows; mean is linear) ----
        float gsum = 0.f;
#pragma unroll 1
        for (int rr = 0; rr < NROWS; rr++) {
            const int* tg = tags + (size_t)(base + rr) * SS;
            const float* embr = em + (size_t)(base + rr) * SS * TT;
#pragma unroll
            for (int q = 0; q < SS / TT; q++) {
                int s = q * TT + j;
                int cur = tg[s];
                int prev = (s == 0) ? START_TAG : tg[s - 1];
                gsum += embr[(size_t)s * TT + cur] + trans[prev * TT + cur];
            }
        }
        if (j < NROWS)
            gsum += trans[tags[(size_t)(base + j) * SS + SS - 1] * TT + END_TAG];
        {
#pragma unroll
            for (int o = 16; o > 0; o >>= 1)
                gsum += __shfl_xor_sync(0xffffffffu, gsum, o);
            __syncthreads();
            if (l == 0) red[w] = gsum;
            __syncthreads();
            if (j == 0)
                g_goldg[grp] = (double)red[0] + (double)red[1] +
                               (double)red[2] + (double)red[3];
        }
    } else {
        // scaled steps consume t = 1022 down to 512
        const float* p1 = em + (size_t)(base + r1) * SS * TT + (size_t)1022 * TT + colq;
        const float* p2 = em + (size_t)(base + r2) * SS * TT + (size_t)1022 * TT + colq;
        scan511<-TT>(&S[0][0], &S[1][0], a0, a1, B0a, B1a, p1, p2,
                     r1, r2, colq, le1, le2);
        // final plain matvec: B_511 = Xtil_512 * E^T (state in S[1])
        u32 A[8][4];
#pragma unroll
        for (int kt = 0; kt < 8; kt++) LDSM4(A[kt], a1 + kt * 32);
        float cL[4][4], cH[4][4];
#pragma unroll
        for (int q = 0; q < 4; q++)
#pragma unroll
            for (int i = 0; i < 4; i++) { cL[q][i] = 0.f; cH[q][i] = 0.f; }
#pragma unroll
        for (int kt = 0; kt < 4; kt++)
#pragma unroll
            for (int q = 0; q < 4; q++) {
                MMA_BF16(cL[q], A[kt],     B0a[q * 8 + kt],     B1a[q * 8 + kt]);
                MMA_BF16(cH[q], A[kt + 4], B0a[q * 8 + kt + 4], B1a[q * 8 + kt + 4]);
            }
#pragma unroll
        for (int q = 0; q < 4; q++) {
            g_bvec[base + r1][colq + 8 * q]     = cL[q][0] + cH[q][0];
            g_bvec[base + r1][colq + 8 * q + 1] = cL[q][1] + cH[q][1];
            g_bvec[base + r2][colq + 8 * q]     = cL[q][2] + cH[q][2];
            g_bvec[base + r2][colq + 8 * q + 1] = cL[q][3] + cH[q][3];
        }
        if (w == 0 && tig == 0) {
            g_leb[base + gid] = le1;
            g_leb[base + gid + 8] = le2;
        }
    }

    // ---- per-group join: second arriver computes the 16 partitions ----
    __threadfence();
    __syncthreads();
    if (j == 0) sjoin = (atomicAdd(&g_cnt[grp], 1u) == 1u) ? 1 : 0;
    __syncthreads();
    if (!sjoin) return;
    __threadfence();
#pragma unroll
    for (int m = 0; m < 4; m++) {
        int row = base + w + 4 * m;
        float pz = 0.f;
#pragma unroll
        for (int t4 = 0; t4 < 4; t4++)
            pz += __ldcg(&g_avec[row][l + 32 * t4]) * __ldcg(&g_bvec[row][l + 32 * t4]);
#pragma unroll
        for (int o = 16; o > 0; o >>= 1)
            pz += __shfl_xor_sync(0xffffffffu, pz, o);
        if (l == 0) {
            int lt = __ldcg(&g_lea[row]) + __ldcg(&g_leb[row]);
            g_part[row] = (double)lt * 0.6931471805599453 + (double)mTE +
                          log((double)pz);
        }
    }
    if (j == 0) g_cnt[grp] = 0;  // reset for graph replay
    __threadfence();
    __syncthreads();
    if (j == 0) sfinal = (atomicAdd(&g_ticket, 1u) == NGRP - 1) ? 1 : 0;
    __syncthreads();
    if (sfinal) {
        __threadfence();
        double d = __ldcg(&g_part[j]) + __ldcg(&g_part[j + 128]);
        if (j < NGRP) d -= __ldcg(&g_goldg[j]);
#pragma unroll
        for (int o = 16; o > 0; o >>= 1)
            d += __shfl_xor_sync(0xffffffffu, d, o);
        if (l == 0) sd[w] = d;
        __syncthreads();
        if (j == 0) {
            out[0] = (float)((sd[0] + sd[1] + sd[2] + sd[3]) * (1.0 / NB));
            g_ticket = 0;  // reset for graph replay
        }
    }
}

extern "C" void kernel_launch(void* const* d_in, const int* in_sizes, int n_in,
                              void* d_out, int out_size) {
    const float* em = (const float*)d_in[0];     // [256,1024,128] f32
    const int* tags = (const int*)d_in[1];       // [256,1024] i32
    const float* trans = (const float*)d_in[2];  // [128,128] f32
    crf_kernel<<<GRID, 128>>>(em, tags, trans, (float*)d_out);
}